// round 1
// baseline (speedup 1.0000x reference)
#include <cuda_runtime.h>
#include <mma.h>

using namespace nvcuda;

// Problem constants
#define B   4
#define S   2048
#define E   2048
#define H   16
#define DH  128
#define BS  (B*S)   // 8192

// Scratch for projected Q/K/V in [b*H+h, S, DH] layout (64 MB each)
__device__ float g_Q[(size_t)B*H*S*DH];
__device__ float g_K[(size_t)B*H*S*DH];
__device__ float g_V[(size_t)B*H*S*DH];

// ---------------------------------------------------------------------------
// Kernel 1: QKV projection GEMM (tf32 WMMA)
//   For z in {q,k,v}: Out[b*H+h][s][d] = sum_e X[b*S+s][e] * W[h][e][d]
//   Block tile: 128(M) x 128(N=DH) x 32(K), 256 threads, 8 warps (4x2),
//   warp tile 32x64 = 2x4 fragments of m16n16k8.
// ---------------------------------------------------------------------------
#define BM 128
#define BN 128
#define BK 32
#define XS_LD 36    // padded leading dims (multiples of 4 floats, 16B rows)
#define WS_LD 132

__global__ __launch_bounds__(256, 1) void qkv_kernel(
    const float* __restrict__ X,
    const float* __restrict__ Wq,
    const float* __restrict__ Wk,
    const float* __restrict__ Wv)
{
    __shared__ float Xs[BM * XS_LD];
    __shared__ float Ws[BK * WS_LD];

    const int h    = blockIdx.x;   // head (fastest -> X tile reused across heads in L2)
    const int mblk = blockIdx.y;   // 128-row block of X
    const int z    = blockIdx.z;   // 0=Q, 1=K, 2=V

    const float* W  = (z == 0 ? Wq : (z == 1 ? Wk : Wv)) + (size_t)h * E * DH;
    float*       Out = (z == 0 ? g_Q : (z == 1 ? g_K : g_V));

    const int tx     = threadIdx.x;
    const int wid    = tx >> 5;
    const int warp_m = wid >> 1;   // 0..3 : 32 rows each
    const int warp_n = wid & 1;    // 0..1 : 64 cols each
    const int m0     = mblk * BM;

    wmma::fragment<wmma::accumulator, 16, 16, 8, float> acc[2][4];
    #pragma unroll
    for (int i = 0; i < 2; i++)
        #pragma unroll
        for (int j = 0; j < 4; j++)
            wmma::fill_fragment(acc[i][j], 0.0f);

    // loader coordinates
    const int xr0 = tx >> 3;          // 0..31 (step 32 rows per chunk)
    const int xc4 = (tx & 7) * 4;     // 0..28 float col
    const int wr0 = tx >> 5;          // 0..7  (step 8 rows per chunk)
    const int wc4 = (tx & 31) * 4;    // 0..124 float col

    const float* Xg = X + (size_t)m0 * E;

    float4 xbuf[4], wbuf[4];
    // preload tile 0
    #pragma unroll
    for (int i = 0; i < 4; i++) {
        xbuf[i] = *(const float4*)(Xg + (size_t)(xr0 + 32 * i) * E + xc4);
        wbuf[i] = *(const float4*)(W  + (size_t)(wr0 + 8 * i) * DH + wc4);
    }

    const int NK = E / BK;  // 64 iterations
    for (int kt = 0; kt < NK; kt++) {
        // commit prefetched tile to smem
        #pragma unroll
        for (int i = 0; i < 4; i++) {
            *(float4*)(Xs + (xr0 + 32 * i) * XS_LD + xc4) = xbuf[i];
            *(float4*)(Ws + (wr0 + 8 * i) * WS_LD + wc4)  = wbuf[i];
        }
        __syncthreads();

        // prefetch next tile into registers (hides DRAM/L2 latency)
        if (kt + 1 < NK) {
            const float* Xn = Xg + (size_t)(kt + 1) * BK;
            const float* Wn = W  + (size_t)(kt + 1) * BK * DH;
            #pragma unroll
            for (int i = 0; i < 4; i++) {
                xbuf[i] = *(const float4*)(Xn + (size_t)(xr0 + 32 * i) * E + xc4);
                wbuf[i] = *(const float4*)(Wn + (size_t)(wr0 + 8 * i) * DH + wc4);
            }
        }

        // 4 k-steps of 8
        #pragma unroll
        for (int kk = 0; kk < 4; kk++) {
            wmma::fragment<wmma::matrix_a, 16, 16, 8, wmma::precision::tf32, wmma::row_major> af[2];
            wmma::fragment<wmma::matrix_b, 16, 16, 8, wmma::precision::tf32, wmma::row_major> bf[4];
            #pragma unroll
            for (int mi = 0; mi < 2; mi++) {
                wmma::load_matrix_sync(af[mi], Xs + (warp_m * 32 + mi * 16) * XS_LD + kk * 8, XS_LD);
                #pragma unroll
                for (int e = 0; e < af[mi].num_elements; e++)
                    af[mi].x[e] = wmma::__float_to_tf32(af[mi].x[e]);
            }
            #pragma unroll
            for (int ni = 0; ni < 4; ni++) {
                wmma::load_matrix_sync(bf[ni], Ws + (kk * 8) * WS_LD + warp_n * 64 + ni * 16, WS_LD);
                #pragma unroll
                for (int e = 0; e < bf[ni].num_elements; e++)
                    bf[ni].x[e] = wmma::__float_to_tf32(bf[ni].x[e]);
            }
            #pragma unroll
            for (int mi = 0; mi < 2; mi++)
                #pragma unroll
                for (int ni = 0; ni < 4; ni++)
                    wmma::mma_sync(acc[mi][ni], af[mi], bf[ni], acc[mi][ni]);
        }
        __syncthreads();
    }

    // epilogue: store to g_{Q,K,V}[(b*H+h), s, d] ; 128-row tile never crosses b
    const int bb = m0 / S;
    const int s0 = m0 % S;
    float* Obase = Out + ((size_t)(bb * H + h) * S + s0) * DH;
    #pragma unroll
    for (int mi = 0; mi < 2; mi++)
        #pragma unroll
        for (int ni = 0; ni < 4; ni++) {
            float* p = Obase + (size_t)(warp_m * 32 + mi * 16) * DH + warp_n * 64 + ni * 16;
            wmma::store_matrix_sync(p, acc[mi][ni], DH, wmma::mem_row_major);
        }
}

// ---------------------------------------------------------------------------
// Kernel 2: causal flash attention, fp32 SIMT
//   grid (S/64, B*H), 256 threads. Thread (r = t/4, c = t%4) owns output row
//   q0+r, cols d = 4*i + c (i = 0..31). Interleaved d-mapping makes every
//   smem read a conflict-free 4-bank broadcast.
// ---------------------------------------------------------------------------
__global__ __launch_bounds__(256, 1) void attn_kernel(float* __restrict__ out)
{
    extern __shared__ float sm[];
    float* Ks = sm;              // 64 x 128
    float* Vs = sm + 64 * 128;   // 64 x 128

    const int qb = blockIdx.x;
    const int bh = blockIdx.y;
    const int b  = bh >> 4;      // H = 16
    const int h  = bh & 15;
    const int q0 = qb * 64;
    const int t  = threadIdx.x;
    const int r  = t >> 2;       // 0..63
    const int c  = t & 3;        // 0..3

    // Q row into registers (d = 4*i + c)
    const float* Qg = g_Q + ((size_t)bh * S + q0 + r) * DH;
    float q[32];
    #pragma unroll
    for (int i = 0; i < 32; i++) q[i] = Qg[4 * i + c];

    float acc[32];
    #pragma unroll
    for (int i = 0; i < 32; i++) acc[i] = 0.0f;
    float mrow = -3.0e38f, lrow = 0.0f;

    const float scale = 0.08838834764831845f;  // 1/sqrt(128)

    for (int kb = 0; kb <= qb; kb++) {
        const int k0 = kb * 64;
        const float4* Kg = (const float4*)(g_K + ((size_t)bh * S + k0) * DH);
        const float4* Vg = (const float4*)(g_V + ((size_t)bh * S + k0) * DH);

        __syncthreads();   // previous tile fully consumed
        #pragma unroll
        for (int i = 0; i < 8; i++) {
            ((float4*)Ks)[t + 256 * i] = Kg[t + 256 * i];
            ((float4*)Vs)[t + 256 * i] = Vg[t + 256 * i];
        }
        __syncthreads();

        // scores: s[j] = (Q[r] . K[j]) * scale  (4-lane split over d, bfly reduce)
        float s[64];
        #pragma unroll
        for (int j = 0; j < 64; j++) {
            float p0 = 0.f, p1 = 0.f, p2 = 0.f, p3 = 0.f;
            const float* kr = Ks + j * 128 + c;
            #pragma unroll
            for (int i = 0; i < 32; i += 4) {
                p0 += q[i]     * kr[4 * i];
                p1 += q[i + 1] * kr[4 * i + 4];
                p2 += q[i + 2] * kr[4 * i + 8];
                p3 += q[i + 3] * kr[4 * i + 12];
            }
            float pv = (p0 + p1) + (p2 + p3);
            pv += __shfl_xor_sync(0xffffffffu, pv, 1);
            pv += __shfl_xor_sync(0xffffffffu, pv, 2);
            s[j] = pv * scale;
        }

        if (kb == qb) {  // diagonal tile: causal mask (k0 == q0 here)
            #pragma unroll
            for (int j = 0; j < 64; j++)
                if (j > r) s[j] = -3.0e38f;
        }

        // online softmax
        float mnew = mrow;
        #pragma unroll
        for (int j = 0; j < 64; j++) mnew = fmaxf(mnew, s[j]);
        const float corr = __expf(mrow - mnew);
        lrow *= corr;
        #pragma unroll
        for (int i = 0; i < 32; i++) acc[i] *= corr;
        mrow = mnew;

        #pragma unroll
        for (int j = 0; j < 64; j++) {
            const float p = __expf(s[j] - mnew);
            lrow += p;
            const float* vr = Vs + j * 128 + c;
            #pragma unroll
            for (int i = 0; i < 32; i++)
                acc[i] += p * vr[4 * i];
        }
    }

    // epilogue: normalize, round(x, 4) like the reference, write [B,S,H*DH]
    const float inv = 1.0f / lrow;
    float* Og = out + (size_t)(b * S + q0 + r) * (H * DH) + h * DH + c;
    #pragma unroll
    for (int i = 0; i < 32; i++) {
        float v = acc[i] * inv;
        v = rintf(v * 1.0e4f) * 1.0e-4f;
        Og[4 * i] = v;
    }
}

// ---------------------------------------------------------------------------
extern "C" void kernel_launch(void* const* d_in, const int* in_sizes, int n_in,
                              void* d_out, int out_size)
{
    const float* X  = (const float*)d_in[0];
    const float* Wq = (const float*)d_in[1];
    const float* Wk = (const float*)d_in[2];
    const float* Wv = (const float*)d_in[3];
    float* out = (float*)d_out;

    // 64 KB dynamic smem for the attention kernel (idempotent, capture-safe)
    cudaFuncSetAttribute(attn_kernel, cudaFuncAttributeMaxDynamicSharedMemorySize, 65536);

    dim3 g1(H, BS / BM, 3);
    qkv_kernel<<<g1, 256>>>(X, Wq, Wk, Wv);

    dim3 g2(S / 64, B * H);
    attn_kernel<<<g2, 256, 65536>>>(out);
}